// round 17
// baseline (speedup 1.0000x reference)
#include <cuda_runtime.h>
#include <cuda_bf16.h>

#define T_IN   4096
#define T2     8192
#define C_CH   512
#define B_N    16
#define THREADS 128
#define TOUT    8
#define SEGS   4
#define SXN    1048    // staged x: raw [start-12, start+1035], edge-clamped (262 float4)

// kaiser_sinc_filter1d(0.25, 0.3, 12) — precomputed, symmetric (h[k]==h[11-k]).
#define H0 0.00202897f
#define H1 0.00938893f
#define H2 (-0.02554347f)
#define H3 (-0.05765742f)
#define H4 0.12857272f
#define H5 0.44321013f

// even u=2s:   y = sum_m UE[m]*x[s+m-3],  UE[m] = 2*h[11-2m]
// odd  u=2s+1: y = sum_m UO[m]*x[s+m-2],  UO[m] = 2*h[10-2m]
__device__ constexpr float UE[6] = { 2.0f*H0, 2.0f*H2, 2.0f*H4, 2.0f*H5, 2.0f*H3, 2.0f*H1 };
__device__ constexpr float UO[6] = { 2.0f*H1, 2.0f*H3, 2.0f*H5, 2.0f*H4, 2.0f*H2, 2.0f*H0 };
__device__ constexpr float DD[12] = { H0, H1, H2, H3, H4, H5, H5, H4, H3, H2, H1, H0 };

__global__ __launch_bounds__(THREADS, 10)   // ~51-reg budget; keep y/rcv/acc resident
void aa_act_kernel(const float* __restrict__ x,
                   const float* __restrict__ alpha,
                   const float* __restrict__ beta,
                   const float* __restrict__ uf,   // unused: taps are immediates
                   const float* __restrict__ df,   // unused
                   float* __restrict__ out)
{
    __shared__ __align__(16) float sx[SXN];

    const int bx    = blockIdx.x;
    const int r     = bx >> 2;        // row = b*C + c
    const int seg   = bx & 3;
    const int start = seg << 10;
    const int c     = r & (C_CH - 1);
    const int tid   = threadIdx.x;
    const int base  = start - 12;     // raw x index of sx[0]

    const float* xrow = x + (size_t)r * T_IN;
    float* orow       = out + (size_t)r * T_IN;

    // ---- Vectorized staging: sx[i] = x[clamp(base+i)]  (base float4-aligned) ----
    {
        float4* dst4 = reinterpret_cast<float4*>(sx);
        if (seg == 0) {
            const float4* s4p = reinterpret_cast<const float4*>(xrow);
#pragma unroll
            for (int it = 0; it < 3; ++it) {
                int i = tid + it * THREADS;
                if (i < 259) dst4[i + 3] = __ldg(s4p + i);
            }
            if (tid < 12) sx[tid] = __ldg(xrow);
        } else if (seg == 3) {
            const float4* s4p = reinterpret_cast<const float4*>(xrow + 3060);
#pragma unroll
            for (int it = 0; it < 3; ++it) {
                int i = tid + it * THREADS;
                if (i < 259) dst4[i] = __ldg(s4p + i);
            }
            if (tid < 12) sx[1036 + tid] = __ldg(xrow + (T_IN - 1));
        } else {
            const float4* s4p = reinterpret_cast<const float4*>(xrow + (start - 12));
#pragma unroll
            for (int it = 0; it < 3; ++it) {
                int i = tid + it * THREADS;
                if (i < 262) dst4[i] = __ldg(s4p + i);
            }
        }
    }

    const float ea    = __expf(__ldg(alpha + c));
    const float ieb   = 1.0f / (__expf(__ldg(beta + c)) + 1e-9f);
    const float ea2   = 2.0f * ea;     // snake uses cos(2*ea*y)
    const float ieb2  = 0.5f * ieb;    // snake: y + ieb2 - ieb2*cos(2*ea*y)
    const float nieb2 = -ieb2;

    __syncthreads();

    // ---- Pass A (all threads): 16 unique y values.
    // sy-index j = 16*tid + jj, u = 2*start - 8 + j.
    //   jj = 2i   (u even): ye = sum_m UE[m]*rx[i+1+m]
    //   jj = 2i+1 (u odd) : yo = sum_m UO[m]*rx[i+2+m]
    // rx[k] = sx[8*tid+4+k]  (float4 index 2*tid+1, 16B aligned)
    float y[16];
    {
        float rx[16];
        const float4* s4 = reinterpret_cast<const float4*>(sx);
#pragma unroll
        for (int i = 0; i < 4; i++) {
            float4 v = s4[2 * tid + 1 + i];
            rx[4 * i + 0] = v.x; rx[4 * i + 1] = v.y;
            rx[4 * i + 2] = v.z; rx[4 * i + 3] = v.w;
        }
#pragma unroll
        for (int i = 0; i < 8; ++i) {
            float ye = UE[0] * rx[i + 1];
            float yo = UO[0] * rx[i + 2];
#pragma unroll
            for (int m = 1; m < 6; ++m) {
                ye = fmaf(UE[m], rx[i + 1 + m], ye);
                yo = fmaf(UO[m], rx[i + 2 + m], yo);
            }
            float ce = __cosf(ye * ea2);
            float co = __cosf(yo * ea2);
            y[2 * i]     = fmaf(nieb2, ce, ye);
            y[2 * i + 1] = fmaf(nieb2, co, yo);
        }
    }

    // ---- Scatter own y (joff = jj, tap k = jj - 3 - 2q).
    float acc[TOUT];
#pragma unroll
    for (int q = 0; q < TOUT; q++) acc[q] = ieb2;   // folded snake constant
#pragma unroll
    for (int jj = 3; jj < 16; ++jj) {
#pragma unroll
        for (int q = 0; q < TOUT; ++q) {
            const int k = jj - 3 - 2 * q;
            if (k >= 0 && k < 12) acc[q] = fmaf(DD[k], y[jj], acc[q]);
        }
    }

    // ---- Fetch neighbor's y[0..12] via warp shuffle (joff = 16 + jj).
    float rcv[13];
#pragma unroll
    for (int jj = 0; jj < 13; ++jj)
        rcv[jj] = __shfl_down_sync(0xffffffffu, y[jj], 1);

    // Lane 31: no in-warp neighbor — recompute the 13 values from sx.
    // Neighbor thread index tn = tid+1; rx'[k] = sx[8*tn+4+k] = sx[8*tid+12+k].
    // (For tid==127 this reads sx[1028..1047], inside the halo.)
    if ((tid & 31) == 31) {
        const int so = 8 * tid + 12;
#pragma unroll
        for (int i = 0; i < 7; ++i) {
            float ye = UE[0] * sx[so + i + 1];
#pragma unroll
            for (int m = 1; m < 6; ++m) ye = fmaf(UE[m], sx[so + i + 1 + m], ye);
            float ce = __cosf(ye * ea2);
            rcv[2 * i] = fmaf(nieb2, ce, ye);
            if (i < 6) {
                float yo = UO[0] * sx[so + i + 2];
#pragma unroll
                for (int m = 1; m < 6; ++m) yo = fmaf(UO[m], sx[so + i + 2 + m], yo);
                float co = __cosf(yo * ea2);
                rcv[2 * i + 1] = fmaf(nieb2, co, yo);
            }
        }
    }

    // ---- Scatter received y (joff = 16+jj, tap k = 13 + jj - 2q).
#pragma unroll
    for (int jj = 0; jj < 13; ++jj) {
#pragma unroll
        for (int q = 0; q < TOUT; ++q) {
            const int k = 13 + jj - 2 * q;
            if (k >= 0 && k < 12) acc[q] = fmaf(DD[k], rcv[jj], acc[q]);
        }
    }

    const int t0 = start + tid * TOUT;
    const bool fast_ok = (t0 >= 3) && (t0 <= 4085);

    if (fast_ok) {
        *reinterpret_cast<float4*>(orow + t0)     = make_float4(acc[0], acc[1], acc[2], acc[3]);
        *reinterpret_cast<float4*>(orow + t0 + 4) = make_float4(acc[4], acc[5], acc[6], acc[7]);
    } else {
        // Edge path (t0==0 or t0==4088): recompute with y-index clamping (champion code).
        float ac2[TOUT];
#pragma unroll
        for (int q = 0; q < TOUT; q++) ac2[q] = ieb2;

#pragma unroll 1
        for (int j = 0; j < 26; ++j) {
            int u = 2 * t0 - 5 + j;
            u = u < 0 ? 0 : (u > T2 - 1 ? T2 - 1 : u);
            const int s   = u >> 1;
            const int idx = s - base;          // sx index of x[s]
            float yv;
            if (u & 1) {
                yv = UO[0] * sx[idx - 2];
#pragma unroll
                for (int m = 1; m < 6; ++m) yv = fmaf(UO[m], sx[idx + m - 2], yv);
            } else {
                yv = UE[0] * sx[idx - 3];
#pragma unroll
                for (int m = 1; m < 6; ++m) yv = fmaf(UE[m], sx[idx + m - 3], yv);
            }
            float cc = __cosf(yv * ea2);
            yv = fmaf(nieb2, cc, yv);
#pragma unroll
            for (int q = 0; q < TOUT; ++q) {
                const int k = j - 2 * q;
                if (k >= 0 && k < 12) ac2[q] = fmaf(DD[k], yv, ac2[q]);
            }
        }
#pragma unroll
        for (int q = 0; q < TOUT; q++) orow[t0 + q] = ac2[q];
    }
}

extern "C" void kernel_launch(void* const* d_in, const int* in_sizes, int n_in,
                              void* d_out, int out_size) {
    const float* x     = (const float*)d_in[0];
    const float* alpha = (const float*)d_in[1];
    const float* beta  = (const float*)d_in[2];
    const float* uf    = (const float*)d_in[3];
    const float* df    = (const float*)d_in[4];
    float* out = (float*)d_out;

    dim3 grid(B_N * C_CH * SEGS);   // 32768 blocks
    aa_act_kernel<<<grid, THREADS>>>(x, alpha, beta, uf, df, out);
}